// round 1
// baseline (speedup 1.0000x reference)
#include <cuda_runtime.h>
#include <math_constants.h>

// Problem constants (fixed shapes per reference):
//   h_P : [16384, 100] f32
//   h   : [16384]      f32
//   volP: [8192, 100]  f32
// Output f32 buffer of 32768 elems:
//   [0      : 8192 )  tot_ind_val
//   [8192   : 16384)  tot_ind (as float)
//   [16384  : 32768)  g = bincount(tot_ind)/8192

#define NUM_P   16384
#define DIM     100
#define KQ      25      // DIM / 4
#define BATN    8192
#define BM      128     // p-tile rows
#define BN      64      // n-tile columns
#define NTHREADS 256

// dynamic smem layout (floats):
//   Xs [DIM][BN]   = 6400
//   Ps [DIM][BM]   = 12800
//   hs [BM]        = 128
#define SMEM_FLOATS (DIM*BN + DIM*BM + BM)

__global__ void zero_g_kernel(float* __restrict__ g) {
    int i = blockIdx.x * blockDim.x + threadIdx.x;
    if (i < NUM_P) g[i] = 0.0f;
}

__global__ __launch_bounds__(NTHREADS, 1)
void ot_argmax_kernel(const float* __restrict__ P,
                      const float* __restrict__ h,
                      const float* __restrict__ X,
                      float* __restrict__ out) {
    extern __shared__ float smem[];
    float* Xs = smem;                 // [DIM][BN]  k-major
    float* Ps = smem + DIM * BN;      // [DIM][BM]  k-major
    float* hs = Ps + DIM * BM;        // [BM]

    const int tid = threadIdx.x;
    const int tx  = tid & 15;         // n-group: columns tx*4 .. tx*4+3
    const int ty  = tid >> 4;         // p-group: rows    ty*8 .. ty*8+7
    const int nbase = blockIdx.x * BN;

    // ---- Load X tile once: volP rows (nbase..nbase+63) transposed into Xs[k][n]
    // Rows are 100 floats = 25 float4 (400B, 16B-aligned).
    for (int idx = tid; idx < KQ * BN; idx += NTHREADS) {
        int kq  = idx >> 6;           // 0..24
        int col = idx & 63;           // 0..63
        float4 v = reinterpret_cast<const float4*>(X)[(nbase + col) * KQ + kq];
        Xs[(4*kq + 0) * BN + col] = v.x;
        Xs[(4*kq + 1) * BN + col] = v.y;
        Xs[(4*kq + 2) * BN + col] = v.z;
        Xs[(4*kq + 3) * BN + col] = v.w;
    }

    float bestv[4];
    int   besti[4];
#pragma unroll
    for (int i = 0; i < 4; i++) { bestv[i] = -CUDART_INF_F; besti[i] = 0; }

    for (int pt = 0; pt < NUM_P; pt += BM) {
        __syncthreads();   // protect Ps/hs from previous iteration's readers
        // ---- Load P tile transposed into Ps[k][p]
        for (int idx = tid; idx < KQ * BM; idx += NTHREADS) {
            int kq  = idx >> 7;       // 0..24
            int row = idx & 127;      // 0..127
            float4 v = reinterpret_cast<const float4*>(P)[(pt + row) * KQ + kq];
            Ps[(4*kq + 0) * BM + row] = v.x;
            Ps[(4*kq + 1) * BM + row] = v.y;
            Ps[(4*kq + 2) * BM + row] = v.z;
            Ps[(4*kq + 3) * BM + row] = v.w;
        }
        if (tid < BM) hs[tid] = h[pt + tid];
        __syncthreads();

        // ---- 128x64 score tile, 4n x 8p per thread
        float acc[8][4];
#pragma unroll
        for (int j = 0; j < 8; j++)
#pragma unroll
            for (int i = 0; i < 4; i++) acc[j][i] = 0.0f;

#pragma unroll 4
        for (int k = 0; k < DIM; k++) {
            float4 xv = *reinterpret_cast<const float4*>(&Xs[k * BN + tx * 4]);
            float4 pa = *reinterpret_cast<const float4*>(&Ps[k * BM + ty * 8]);
            float4 pb = *reinterpret_cast<const float4*>(&Ps[k * BM + ty * 8 + 4]);
            float xr[4] = {xv.x, xv.y, xv.z, xv.w};
            float pr[8] = {pa.x, pa.y, pa.z, pa.w, pb.x, pb.y, pb.z, pb.w};
#pragma unroll
            for (int j = 0; j < 8; j++)
#pragma unroll
                for (int i = 0; i < 4; i++)
                    acc[j][i] = fmaf(pr[j], xr[i], acc[j][i]);
        }

        // ---- Fold into running (max, argmax). Ascending p + strict '>' keeps
        // the first maximal index (matches jnp.argmax semantics).
#pragma unroll
        for (int j = 0; j < 8; j++) {
            float hv = hs[ty * 8 + j];
            int   pg = pt + ty * 8 + j;
#pragma unroll
            for (int i = 0; i < 4; i++) {
                float s = acc[j][i] + hv;
                if (s > bestv[i]) { bestv[i] = s; besti[i] = pg; }
            }
        }
    }

    // ---- Cross-thread reduce over the 16 p-groups per column. Reuse Ps memory.
    __syncthreads();
    float* rv = Ps;                       // [BN][16] floats
    int*   ri = reinterpret_cast<int*>(Ps + BN * 16);   // [BN][16] ints
#pragma unroll
    for (int i = 0; i < 4; i++) {
        int n = tx * 4 + i;
        rv[n * 16 + ty] = bestv[i];
        ri[n * 16 + ty] = besti[i];
    }
    __syncthreads();

    if (tid < BN) {
        int n = tid;
        float bv = rv[n * 16];
        int   bi = ri[n * 16];
#pragma unroll
        for (int t = 1; t < 16; t++) {
            float v  = rv[n * 16 + t];
            int   ix = ri[n * 16 + t];
            if (v > bv || (v == bv && ix < bi)) { bv = v; bi = ix; }
        }
        int ng = nbase + n;
        out[ng]        = bv;                 // tot_ind_val
        out[BATN + ng] = (float)bi;          // tot_ind (cast to f32)
        atomicAdd(&out[2 * BATN + bi], 1.0f / (float)BATN);   // g
    }
}

extern "C" void kernel_launch(void* const* d_in, const int* in_sizes, int n_in,
                              void* d_out, int out_size) {
    const float* P = (const float*)d_in[0];   // h_P [16384,100]
    const float* h = (const float*)d_in[1];   // h   [16384]
    const float* X = (const float*)d_in[2];   // volP[8192,100]
    float* out = (float*)d_out;

    (void)in_sizes; (void)n_in; (void)out_size;

    static bool attr_set = false;
    if (!attr_set) {
        cudaFuncSetAttribute(ot_argmax_kernel,
                             cudaFuncAttributeMaxDynamicSharedMemorySize,
                             SMEM_FLOATS * (int)sizeof(float));
        attr_set = true;
    }

    // Zero the g region (d_out is poisoned), then the fused GEMM+argmax.
    zero_g_kernel<<<(NUM_P + 255) / 256, 256>>>(out + 2 * BATN);
    ot_argmax_kernel<<<BATN / BN, NTHREADS, SMEM_FLOATS * sizeof(float)>>>(P, h, X, out);
}